// round 5
// baseline (speedup 1.0000x reference)
#include <cuda_runtime.h>
#include <cuda_bf16.h>
#include <cstdint>

#define NN 100000
#define EE 500000
#define BB 4096
#define HC 128
#define NH 4
#define HID 32
#define EDIM 4

#define SCAN_T 512
#define SCAN_B ((NN + SCAN_T - 1) / SCAN_T)  // 196

// ---------------- scratch (device globals: allocation-free) ----------------
__device__ float          g_q[NN * HC];
__device__ __nv_bfloat16  g_kb[NN * HC];  // k in bf16: halves random-gather traffic
__device__ float          g_v[NN * HC];
__device__ float          g_s[NN * HC];   // skip (x@Ws + bs)
__device__ float          g_h[NN * HC];   // layer output / next-layer input
__device__ float          g_pooled[BB * HC];
__device__ float          g_cnt[BB];
// CSR build
__device__ int    g_deg[NN];
__device__ int    g_incl[NN];
__device__ int    g_rowptr[NN + 1];
__device__ int    g_cursor[NN];
__device__ int    g_bsum[SCAN_B];
__device__ int    g_boff[SCAN_B];
__device__ int    g_esrc[EE];
__device__ float4 g_eea[EE];

// ---------------- side stream for overlap ----------------
static cudaStream_t g_s2;
static cudaEvent_t g_evA, g_evB;
namespace {
struct StreamInit {
    StreamInit() {
        cudaStreamCreateWithFlags(&g_s2, cudaStreamNonBlocking);
        cudaEventCreateWithFlags(&g_evA, cudaEventDisableTiming);
        cudaEventCreateWithFlags(&g_evB, cudaEventDisableTiming);
    }
} g_stream_init;
}

// ---------------- helpers ----------------
__device__ __forceinline__ float to_tf32(float x) {
    uint32_t u;
    asm("cvt.rna.tf32.f32 %0, %1;" : "=r"(u) : "f"(x));
    return __uint_as_float(u);
}

__device__ __forceinline__ void mma_tf32(float& c0, float& c1, float& c2, float& c3,
                                         uint32_t a0, uint32_t a1, uint32_t a2, uint32_t a3,
                                         uint32_t b0, uint32_t b1) {
    asm volatile(
        "mma.sync.aligned.m16n8k8.row.col.f32.tf32.tf32.f32 "
        "{%0,%1,%2,%3}, {%4,%5,%6,%7}, {%8,%9}, {%0,%1,%2,%3};"
        : "+f"(c0), "+f"(c1), "+f"(c2), "+f"(c3)
        : "r"(a0), "r"(a1), "r"(a2), "r"(a3), "r"(b0), "r"(b1));
}

// ---------------- CSR build ----------------
__global__ void zero_deg_kernel() {
    int stride = gridDim.x * blockDim.x;
    for (int i = blockIdx.x * blockDim.x + threadIdx.x; i < NN; i += stride) g_deg[i] = 0;
}

__global__ void hist_kernel(const int* __restrict__ ei) {
    int stride = gridDim.x * blockDim.x;
    for (int e = blockIdx.x * blockDim.x + threadIdx.x; e < EE; e += stride)
        atomicAdd(&g_deg[ei[EE + e]], 1);
}

__global__ void scanA_kernel() {
    __shared__ int s[SCAN_T];
    int tid = threadIdx.x;
    int i = blockIdx.x * SCAN_T + tid;
    int v = (i < NN) ? g_deg[i] : 0;
    s[tid] = v;
    __syncthreads();
#pragma unroll
    for (int off = 1; off < SCAN_T; off <<= 1) {
        int t = (tid >= off) ? s[tid - off] : 0;
        __syncthreads();
        s[tid] += t;
        __syncthreads();
    }
    if (i < NN) g_incl[i] = s[tid];
    if (tid == SCAN_T - 1) g_bsum[blockIdx.x] = s[tid];
}

__global__ void scanB_kernel() {
    __shared__ int s[256];
    int tid = threadIdx.x;
    int v = (tid < SCAN_B) ? g_bsum[tid] : 0;
    s[tid] = v;
    __syncthreads();
#pragma unroll
    for (int off = 1; off < 256; off <<= 1) {
        int t = (tid >= off) ? s[tid - off] : 0;
        __syncthreads();
        s[tid] += t;
        __syncthreads();
    }
    if (tid < SCAN_B) g_boff[tid] = s[tid] - v;
}

__global__ void scanC_kernel() {
    int i = blockIdx.x * SCAN_T + threadIdx.x;
    if (i < NN) {
        int excl = g_incl[i] - g_deg[i] + g_boff[blockIdx.x];
        g_rowptr[i] = excl;
        g_cursor[i] = excl;
    }
    if (i == 0) g_rowptr[NN] = EE;
}

__global__ void bucket_kernel(const int* __restrict__ ei, const float* __restrict__ ea) {
    int stride = gridDim.x * blockDim.x;
    for (int e = blockIdx.x * blockDim.x + threadIdx.x; e < EE; e += stride) {
        int dst = ei[EE + e];
        int pos = atomicAdd(&g_cursor[dst], 1);
        g_esrc[pos] = ei[e];
        g_eea[pos] = reinterpret_cast<const float4*>(ea)[e];
    }
}

// ---------------- zero pool + count ----------------
__global__ void zero_pool_kernel() {
    int stride = gridDim.x * blockDim.x;
    int i0 = blockIdx.x * blockDim.x + threadIdx.x;
    for (int i = i0; i < BB * HC; i += stride) g_pooled[i] = 0.f;
    for (int i = i0; i < BB; i += stride) g_cnt[i] = 0.f;
}

__global__ void cnt_kernel(const int* __restrict__ batch) {
    int n = blockIdx.x * blockDim.x + threadIdx.x;
    if (n < NN) atomicAdd(&g_cnt[batch[n]], 1.f);
}

// ---------------- tensor-core fused q/k/v/skip GEMM ----------------
template <int D, bool USE_H>
__global__ __launch_bounds__(256) void gemm_tc_kernel(
    const float* __restrict__ x,
    const float* __restrict__ Wq, const float* __restrict__ bq,
    const float* __restrict__ Wk, const float* __restrict__ bk,
    const float* __restrict__ Wv, const float* __restrict__ bv,
    const float* __restrict__ Ws, const float* __restrict__ bs) {
    __shared__ float xs[128][36];
    __shared__ float ws[32][136];

    const float* xin = USE_H ? g_h : x;
    const float* W;
    const float* bias;
    float* out;
    int m = blockIdx.y;
    if (m == 0)      { W = Wq; bias = bq; out = g_q; }
    else if (m == 1) { W = Wk; bias = bk; out = nullptr; }  // k -> bf16 path
    else if (m == 2) { W = Wv; bias = bv; out = g_v; }
    else             { W = Ws; bias = bs; out = g_s; }

    int node0 = blockIdx.x * 128;
    int tid = threadIdx.x;
    int lane = tid & 31, wid = tid >> 5;
    int warp_m = wid >> 2, warp_n = wid & 3;
    int gID = lane >> 2, t4 = lane & 3;

    const int xr_r[4] = {(tid + 0) >> 3, (tid + 256) >> 3, (tid + 512) >> 3, (tid + 768) >> 3};
    const int xr_c = (tid & 7) * 4;
    const int wr_r[4] = {(tid + 0) >> 5, (tid + 256) >> 5, (tid + 512) >> 5, (tid + 768) >> 5};
    const int wr_c = (tid & 31) * 4;

    float4 xr[4], wr[4];
    auto load_chunk = [&](int k0) {
#pragma unroll
        for (int t = 0; t < 4; t++) {
            int n = node0 + xr_r[t];
            xr[t] = (n < NN) ? *(const float4*)&xin[n * D + k0 + xr_c]
                             : make_float4(0.f, 0.f, 0.f, 0.f);
            wr[t] = *(const float4*)&W[(k0 + wr_r[t]) * HC + wr_c];
        }
    };
    auto store_chunk = [&]() {
#pragma unroll
        for (int t = 0; t < 4; t++) {
            float* xp = &xs[xr_r[t]][xr_c];
            xp[0] = to_tf32(xr[t].x); xp[1] = to_tf32(xr[t].y);
            xp[2] = to_tf32(xr[t].z); xp[3] = to_tf32(xr[t].w);
            float* wp = &ws[wr_r[t]][wr_c];
            wp[0] = to_tf32(wr[t].x); wp[1] = to_tf32(wr[t].y);
            wp[2] = to_tf32(wr[t].z); wp[3] = to_tf32(wr[t].w);
        }
    };

    float acc[4][4][4];
#pragma unroll
    for (int mi = 0; mi < 4; mi++)
#pragma unroll
        for (int ni = 0; ni < 4; ni++)
#pragma unroll
            for (int r = 0; r < 4; r++) acc[mi][ni][r] = 0.f;

    load_chunk(0);
#pragma unroll
    for (int k0 = 0; k0 < D; k0 += 32) {
        store_chunk();
        __syncthreads();
        if (k0 + 32 < D) load_chunk(k0 + 32);

#pragma unroll
        for (int ks = 0; ks < 4; ks++) {
            int kk = ks * 8;
            uint32_t a[4][4], bf[4][2];
#pragma unroll
            for (int mi = 0; mi < 4; mi++) {
                int row = warp_m * 64 + mi * 16 + gID;
                a[mi][0] = __float_as_uint(xs[row][kk + t4]);
                a[mi][1] = __float_as_uint(xs[row + 8][kk + t4]);
                a[mi][2] = __float_as_uint(xs[row][kk + t4 + 4]);
                a[mi][3] = __float_as_uint(xs[row + 8][kk + t4 + 4]);
            }
#pragma unroll
            for (int ni = 0; ni < 4; ni++) {
                int col = warp_n * 32 + ni * 8 + gID;
                bf[ni][0] = __float_as_uint(ws[kk + t4][col]);
                bf[ni][1] = __float_as_uint(ws[kk + t4 + 4][col]);
            }
#pragma unroll
            for (int mi = 0; mi < 4; mi++)
#pragma unroll
                for (int ni = 0; ni < 4; ni++)
                    mma_tf32(acc[mi][ni][0], acc[mi][ni][1], acc[mi][ni][2], acc[mi][ni][3],
                             a[mi][0], a[mi][1], a[mi][2], a[mi][3],
                             bf[ni][0], bf[ni][1]);
        }
        __syncthreads();
    }

#pragma unroll
    for (int mi = 0; mi < 4; mi++) {
        int r0 = node0 + warp_m * 64 + mi * 16 + gID;
#pragma unroll
        for (int ni = 0; ni < 4; ni++) {
            int cb = warp_n * 32 + ni * 8 + 2 * t4;
            float b0v = bias[cb], b1v = bias[cb + 1];
            if (m == 1) {  // k: store bf16
                if (r0 < NN) {
                    g_kb[r0 * HC + cb]     = __float2bfloat16(acc[mi][ni][0] + b0v);
                    g_kb[r0 * HC + cb + 1] = __float2bfloat16(acc[mi][ni][1] + b1v);
                }
                if (r0 + 8 < NN) {
                    g_kb[(r0 + 8) * HC + cb]     = __float2bfloat16(acc[mi][ni][2] + b0v);
                    g_kb[(r0 + 8) * HC + cb + 1] = __float2bfloat16(acc[mi][ni][3] + b1v);
                }
            } else {
                if (r0 < NN) {
                    out[r0 * HC + cb] = acc[mi][ni][0] + b0v;
                    out[r0 * HC + cb + 1] = acc[mi][ni][1] + b1v;
                }
                if (r0 + 8 < NN) {
                    out[(r0 + 8) * HC + cb] = acc[mi][ni][2] + b0v;
                    out[(r0 + 8) * HC + cb + 1] = acc[mi][ni][3] + b1v;
                }
            }
        }
    }
}

// ---------------- per-node fused edge pass (gather, no atomics) ----------------
// One warp per destination node; 3-way edge unroll for gather MLP.
template <bool RELU, bool POOL>
__global__ __launch_bounds__(256) void node_edge_kernel(const float* __restrict__ We,
                                                        const int* __restrict__ batch) {
    __shared__ float Wes[EDIM * HC];
    for (int i = threadIdx.x; i < EDIM * HC; i += blockDim.x) Wes[i] = We[i];
    __syncthreads();

    int n = blockIdx.x * 8 + (threadIdx.x >> 5);
    int lane = threadIdx.x & 31;
    if (n >= NN) return;

    int r0 = g_rowptr[n];
    int r1 = g_rowptr[n + 1];

    float qv[NH], acc[NH], asum[NH];
#pragma unroll
    for (int j = 0; j < NH; j++) {
        qv[j] = g_q[n * HC + j * HID + lane];
        acc[j] = 0.f;
        asum[j] = 0.f;
    }

    float w0 = Wes[lane], w1 = Wes[HC + lane], w2 = Wes[2 * HC + lane], w3 = Wes[3 * HC + lane];
    float W0[NH], W1[NH], W2[NH], W3[NH];
#pragma unroll
    for (int j = 0; j < NH; j++) {
        int c = j * HID + lane;
        W0[j] = Wes[c]; W1[j] = Wes[HC + c]; W2[j] = Wes[2 * HC + c]; W3[j] = Wes[3 * HC + c];
    }
    (void)w0; (void)w1; (void)w2; (void)w3;

    int i = r0;
    for (; i + 2 < r1; i += 3) {
        int s0 = g_esrc[i], s1 = g_esrc[i + 1], s2 = g_esrc[i + 2];
        float4 a0 = g_eea[i], a1 = g_eea[i + 1], a2 = g_eea[i + 2];
        float k0[NH], v0[NH], k1[NH], v1[NH], k2[NH], v2[NH];
#pragma unroll
        for (int j = 0; j < NH; j++) {
            int c = j * HID + lane;
            k0[j] = __bfloat162float(g_kb[s0 * HC + c]);
            k1[j] = __bfloat162float(g_kb[s1 * HC + c]);
            k2[j] = __bfloat162float(g_kb[s2 * HC + c]);
            v0[j] = g_v[s0 * HC + c];
            v1[j] = g_v[s1 * HC + c];
            v2[j] = g_v[s2 * HC + c];
        }
        float e0[NH], e1[NH], e2[NH], p0[NH], p1[NH], p2[NH];
#pragma unroll
        for (int j = 0; j < NH; j++) {
            e0[j] = a0.x * W0[j] + a0.y * W1[j] + a0.z * W2[j] + a0.w * W3[j];
            e1[j] = a1.x * W0[j] + a1.y * W1[j] + a1.z * W2[j] + a1.w * W3[j];
            e2[j] = a2.x * W0[j] + a2.y * W1[j] + a2.z * W2[j] + a2.w * W3[j];
            p0[j] = qv[j] * (k0[j] + e0[j]);
            p1[j] = qv[j] * (k1[j] + e1[j]);
            p2[j] = qv[j] * (k2[j] + e2[j]);
        }
#pragma unroll
        for (int off = 16; off; off >>= 1) {
#pragma unroll
            for (int j = 0; j < NH; j++) {
                p0[j] += __shfl_xor_sync(0xffffffffu, p0[j], off);
                p1[j] += __shfl_xor_sync(0xffffffffu, p1[j], off);
                p2[j] += __shfl_xor_sync(0xffffffffu, p2[j], off);
            }
        }
#pragma unroll
        for (int j = 0; j < NH; j++) {
            float al0 = __expf(p0[j] * 0.17677669529663687f);
            float al1 = __expf(p1[j] * 0.17677669529663687f);
            float al2 = __expf(p2[j] * 0.17677669529663687f);
            asum[j] += al0 + al1 + al2;
            acc[j] = fmaf(v0[j] + e0[j], al0, acc[j]);
            acc[j] = fmaf(v1[j] + e1[j], al1, acc[j]);
            acc[j] = fmaf(v2[j] + e2[j], al2, acc[j]);
        }
    }
    for (; i < r1; i++) {
        int s0 = g_esrc[i];
        float4 a0 = g_eea[i];
        float k0[NH], v0[NH], e0[NH], p0[NH];
#pragma unroll
        for (int j = 0; j < NH; j++) {
            int c = j * HID + lane;
            k0[j] = __bfloat162float(g_kb[s0 * HC + c]);
            v0[j] = g_v[s0 * HC + c];
        }
#pragma unroll
        for (int j = 0; j < NH; j++) {
            e0[j] = a0.x * W0[j] + a0.y * W1[j] + a0.z * W2[j] + a0.w * W3[j];
            p0[j] = qv[j] * (k0[j] + e0[j]);
        }
#pragma unroll
        for (int j = 0; j < NH; j++) {
#pragma unroll
            for (int off = 16; off; off >>= 1) p0[j] += __shfl_xor_sync(0xffffffffu, p0[j], off);
        }
#pragma unroll
        for (int j = 0; j < NH; j++) {
            float al = __expf(p0[j] * 0.17677669529663687f);
            asum[j] += al;
            acc[j] = fmaf(v0[j] + e0[j], al, acc[j]);
        }
    }

    int bslot = POOL ? batch[n] : 0;
#pragma unroll
    for (int j = 0; j < NH; j++) {
        int c = j * HID + lane;
        float h = acc[j] / (asum[j] + 1e-16f) + g_s[n * HC + c];
        if (RELU) h = fmaxf(h, 0.f);
        if (POOL) atomicAdd(&g_pooled[bslot * HC + c], h);
        else g_h[n * HC + c] = h;
    }
}

// ---------------- head ----------------
__global__ void head_kernel(const int* __restrict__ rt,
                            const float* __restrict__ hW,
                            const float* __restrict__ hb,
                            float* __restrict__ out) {
    int b = (blockIdx.x * blockDim.x + threadIdx.x) >> 5;
    int lane = threadIdx.x & 31;
    if (b >= BB) return;
    int r = rt[b];
    float acc = 0.f;
#pragma unroll
    for (int j = 0; j < NH; j++) {
        int c = j * HID + lane;
        acc = fmaf(g_pooled[b * HC + c], hW[r * HC + c], acc);
    }
#pragma unroll
    for (int off = 16; off; off >>= 1) acc += __shfl_xor_sync(0xffffffffu, acc, off);
    if (lane == 0) {
        float cnt = fmaxf(g_cnt[b], 1.f);
        out[b] = acc / cnt + hb[r];
    }
}

// ---------------- launch ----------------
extern "C" void kernel_launch(void* const* d_in, const int* in_sizes, int n_in,
                              void* d_out, int out_size) {
    const float* x     = (const float*)d_in[0];
    const int*   ei    = (const int*)d_in[1];
    const float* ea    = (const float*)d_in[2];
    const int*   batch = (const int*)d_in[3];
    const int*   rt    = (const int*)d_in[4];
    const float* Wq1 = (const float*)d_in[5];
    const float* bq1 = (const float*)d_in[6];
    const float* Wk1 = (const float*)d_in[7];
    const float* bk1 = (const float*)d_in[8];
    const float* Wv1 = (const float*)d_in[9];
    const float* bv1 = (const float*)d_in[10];
    const float* We1 = (const float*)d_in[11];
    const float* Ws1 = (const float*)d_in[12];
    const float* bs1 = (const float*)d_in[13];
    const float* Wq23 = (const float*)d_in[14];
    const float* bq23 = (const float*)d_in[15];
    const float* Wk23 = (const float*)d_in[16];
    const float* bk23 = (const float*)d_in[17];
    const float* Wv23 = (const float*)d_in[18];
    const float* bv23 = (const float*)d_in[19];
    const float* We23 = (const float*)d_in[20];
    const float* Ws23 = (const float*)d_in[21];
    const float* bs23 = (const float*)d_in[22];
    const float* headW = (const float*)d_in[23];
    const float* headb = (const float*)d_in[24];
    float* out = (float*)d_out;

    const dim3 gemm_grid((NN + 127) / 128, 4);
    const int node_blocks = (NN + 7) / 8;

    // ---- fork: CSR build + pool init + counts on side stream ----
    cudaEventRecord(g_evA, 0);
    cudaStreamWaitEvent(g_s2, g_evA, 0);
    zero_deg_kernel<<<256, 256, 0, g_s2>>>();
    hist_kernel<<<1024, 256, 0, g_s2>>>(ei);
    scanA_kernel<<<SCAN_B, SCAN_T, 0, g_s2>>>();
    scanB_kernel<<<1, 256, 0, g_s2>>>();
    scanC_kernel<<<SCAN_B, SCAN_T, 0, g_s2>>>();
    bucket_kernel<<<1024, 256, 0, g_s2>>>(ei, ea);
    zero_pool_kernel<<<256, 256, 0, g_s2>>>();
    cnt_kernel<<<(NN + 255) / 256, 256, 0, g_s2>>>(batch);
    cudaEventRecord(g_evB, g_s2);

    // ---- main stream ----
    gemm_tc_kernel<64, false><<<gemm_grid, 256>>>(x, Wq1, bq1, Wk1, bk1, Wv1, bv1, Ws1, bs1);
    cudaStreamWaitEvent(0, g_evB, 0);

    node_edge_kernel<true, false><<<node_blocks, 256>>>(We1, batch);

    gemm_tc_kernel<128, true><<<gemm_grid, 256>>>(
        x, Wq23, bq23, Wk23, bk23, Wv23, bv23, Ws23, bs23);
    node_edge_kernel<true, false><<<node_blocks, 256>>>(We23, batch);

    gemm_tc_kernel<128, true><<<gemm_grid, 256>>>(
        x, Wq23 + HC * HC, bq23 + HC, Wk23 + HC * HC, bk23 + HC,
        Wv23 + HC * HC, bv23 + HC, Ws23 + HC * HC, bs23 + HC);
    node_edge_kernel<false, true><<<node_blocks, 256>>>(We23 + EDIM * HC, batch);

    head_kernel<<<(BB * 32 + 255) / 256, 256>>>(rt, headW, headb, out);
}

// round 6
// speedup vs baseline: 1.0497x; 1.0497x over previous
#include <cuda_runtime.h>
#include <cstdint>

#define NN 100000
#define EE 500000
#define BB 4096
#define HC 128
#define NH 4
#define HID 32
#define EDIM 4

#define SCAN_T 512
#define SCAN_B ((NN + SCAN_T - 1) / SCAN_T)  // 196

// ---------------- scratch (device globals: allocation-free) ----------------
__device__ float g_q[NN * HC];
__device__ float g_k[NN * HC];
__device__ float g_v[NN * HC];
__device__ float g_s[NN * HC];   // skip (x@Ws + bs)
__device__ float g_h[NN * HC];   // layer output / next-layer input
__device__ float g_pooled[BB * HC];
__device__ float g_cnt[BB];
// CSR build
__device__ int    g_deg[NN];
__device__ int    g_incl[NN];
__device__ int    g_rowptr[NN + 1];
__device__ int    g_cursor[NN];
__device__ int    g_bsum[SCAN_B];
__device__ int    g_boff[SCAN_B];
__device__ int    g_esrc[EE];
__device__ float4 g_eea[EE];

// ---------------- side stream for overlap ----------------
static cudaStream_t g_s2;
static cudaEvent_t g_evA, g_evB;
namespace {
struct StreamInit {
    StreamInit() {
        cudaStreamCreateWithFlags(&g_s2, cudaStreamNonBlocking);
        cudaEventCreateWithFlags(&g_evA, cudaEventDisableTiming);
        cudaEventCreateWithFlags(&g_evB, cudaEventDisableTiming);
    }
} g_stream_init;
}

// ---------------- helpers ----------------
__device__ __forceinline__ float to_tf32(float x) {
    uint32_t u;
    asm("cvt.rna.tf32.f32 %0, %1;" : "=r"(u) : "f"(x));
    return __uint_as_float(u);
}

__device__ __forceinline__ void mma_tf32(float& c0, float& c1, float& c2, float& c3,
                                         uint32_t a0, uint32_t a1, uint32_t a2, uint32_t a3,
                                         uint32_t b0, uint32_t b1) {
    asm volatile(
        "mma.sync.aligned.m16n8k8.row.col.f32.tf32.tf32.f32 "
        "{%0,%1,%2,%3}, {%4,%5,%6,%7}, {%8,%9}, {%0,%1,%2,%3};"
        : "+f"(c0), "+f"(c1), "+f"(c2), "+f"(c3)
        : "r"(a0), "r"(a1), "r"(a2), "r"(a3), "r"(b0), "r"(b1));
}

// ---------------- CSR build ----------------
__global__ void zero_deg_kernel() {
    int stride = gridDim.x * blockDim.x;
    for (int i = blockIdx.x * blockDim.x + threadIdx.x; i < NN; i += stride) g_deg[i] = 0;
}

__global__ void hist_kernel(const int* __restrict__ ei) {
    int stride = gridDim.x * blockDim.x;
    for (int e = blockIdx.x * blockDim.x + threadIdx.x; e < EE; e += stride)
        atomicAdd(&g_deg[ei[EE + e]], 1);
}

__global__ void scanA_kernel() {
    __shared__ int s[SCAN_T];
    int tid = threadIdx.x;
    int i = blockIdx.x * SCAN_T + tid;
    int v = (i < NN) ? g_deg[i] : 0;
    s[tid] = v;
    __syncthreads();
#pragma unroll
    for (int off = 1; off < SCAN_T; off <<= 1) {
        int t = (tid >= off) ? s[tid - off] : 0;
        __syncthreads();
        s[tid] += t;
        __syncthreads();
    }
    if (i < NN) g_incl[i] = s[tid];
    if (tid == SCAN_T - 1) g_bsum[blockIdx.x] = s[tid];
}

__global__ void scanB_kernel() {
    __shared__ int s[256];
    int tid = threadIdx.x;
    int v = (tid < SCAN_B) ? g_bsum[tid] : 0;
    s[tid] = v;
    __syncthreads();
#pragma unroll
    for (int off = 1; off < 256; off <<= 1) {
        int t = (tid >= off) ? s[tid - off] : 0;
        __syncthreads();
        s[tid] += t;
        __syncthreads();
    }
    if (tid < SCAN_B) g_boff[tid] = s[tid] - v;
}

__global__ void scanC_kernel() {
    int i = blockIdx.x * SCAN_T + threadIdx.x;
    if (i < NN) {
        int excl = g_incl[i] - g_deg[i] + g_boff[blockIdx.x];
        g_rowptr[i] = excl;
        g_cursor[i] = excl;
    }
    if (i == 0) g_rowptr[NN] = EE;
}

__global__ void bucket_kernel(const int* __restrict__ ei, const float* __restrict__ ea) {
    int stride = gridDim.x * blockDim.x;
    for (int e = blockIdx.x * blockDim.x + threadIdx.x; e < EE; e += stride) {
        int dst = ei[EE + e];
        int pos = atomicAdd(&g_cursor[dst], 1);
        g_esrc[pos] = ei[e];
        g_eea[pos] = reinterpret_cast<const float4*>(ea)[e];
    }
}

// ---------------- zero pool + count ----------------
__global__ void zero_pool_kernel() {
    int stride = gridDim.x * blockDim.x;
    int i0 = blockIdx.x * blockDim.x + threadIdx.x;
    for (int i = i0; i < BB * HC; i += stride) g_pooled[i] = 0.f;
    for (int i = i0; i < BB; i += stride) g_cnt[i] = 0.f;
}

__global__ void cnt_kernel(const int* __restrict__ batch) {
    int n = blockIdx.x * blockDim.x + threadIdx.x;
    if (n < NN) atomicAdd(&g_cnt[batch[n]], 1.f);
}

// ---------------- tensor-core fused q/k/v/skip GEMM ----------------
// A tile stored k-PERMUTED in smem: element (row,k) at xs[row][(k&3)*8 + (k>>2)],
// row stride 34. The mma a-frag pair (k, k+4) becomes an adjacent float2 ->
// a-frag loads are LDS.64, conflict-free (banks 2*gID + 8*t4 + {0,1}).
template <int D, bool USE_H>
__global__ __launch_bounds__(256) void gemm_tc_kernel(
    const float* __restrict__ x,
    const float* __restrict__ Wq, const float* __restrict__ bq,
    const float* __restrict__ Wk, const float* __restrict__ bk,
    const float* __restrict__ Wv, const float* __restrict__ bv,
    const float* __restrict__ Ws, const float* __restrict__ bs) {
    __shared__ __align__(16) float xs[128][34];
    __shared__ __align__(16) float ws[32][136];

    const float* xin = USE_H ? g_h : x;
    const float* W;
    const float* bias;
    float* out;
    int m = blockIdx.y;
    if (m == 0)      { W = Wq; bias = bq; out = g_q; }
    else if (m == 1) { W = Wk; bias = bk; out = g_k; }
    else if (m == 2) { W = Wv; bias = bv; out = g_v; }
    else             { W = Ws; bias = bs; out = g_s; }

    int node0 = blockIdx.x * 128;
    int tid = threadIdx.x;
    int lane = tid & 31, wid = tid >> 5;
    int warp_m = wid >> 2, warp_n = wid & 3;
    int gID = lane >> 2, t4 = lane & 3;

    const int xr_r[4] = {(tid + 0) >> 3, (tid + 256) >> 3, (tid + 512) >> 3, (tid + 768) >> 3};
    const int xr_c = (tid & 7) * 4;
    const int xq = xr_c >> 2;  // permuted base column
    const int wr_r[4] = {(tid + 0) >> 5, (tid + 256) >> 5, (tid + 512) >> 5, (tid + 768) >> 5};
    const int wr_c = (tid & 31) * 4;

    float4 xr[4], wr[4];
    auto load_chunk = [&](int k0) {
#pragma unroll
        for (int t = 0; t < 4; t++) {
            int n = node0 + xr_r[t];
            xr[t] = (n < NN) ? *(const float4*)&xin[n * D + k0 + xr_c]
                             : make_float4(0.f, 0.f, 0.f, 0.f);
            wr[t] = *(const float4*)&W[(k0 + wr_r[t]) * HC + wr_c];
        }
    };
    auto store_chunk = [&]() {
#pragma unroll
        for (int t = 0; t < 4; t++) {
            // permuted scatter: component d of the float4 goes to column xq + 8d
            float* xp = &xs[xr_r[t]][0];
            xp[xq + 0]  = to_tf32(xr[t].x);
            xp[xq + 8]  = to_tf32(xr[t].y);
            xp[xq + 16] = to_tf32(xr[t].z);
            xp[xq + 24] = to_tf32(xr[t].w);
            float* wp = &ws[wr_r[t]][wr_c];
            wp[0] = to_tf32(wr[t].x); wp[1] = to_tf32(wr[t].y);
            wp[2] = to_tf32(wr[t].z); wp[3] = to_tf32(wr[t].w);
        }
    };

    float acc[4][4][4];
#pragma unroll
    for (int mi = 0; mi < 4; mi++)
#pragma unroll
        for (int ni = 0; ni < 4; ni++)
#pragma unroll
            for (int r = 0; r < 4; r++) acc[mi][ni][r] = 0.f;

    load_chunk(0);
#pragma unroll
    for (int k0 = 0; k0 < D; k0 += 32) {
        store_chunk();
        __syncthreads();
        if (k0 + 32 < D) load_chunk(k0 + 32);

#pragma unroll
        for (int ks = 0; ks < 4; ks++) {
            int kk = ks * 8;
            int pa = t4 * 8 + 2 * ks;  // permuted column of (kk+t4); +1 is (kk+t4+4)
            uint32_t a[4][4], bf[4][2];
#pragma unroll
            for (int mi = 0; mi < 4; mi++) {
                int row = warp_m * 64 + mi * 16 + gID;
                float2 fa = *(const float2*)&xs[row][pa];
                float2 fb = *(const float2*)&xs[row + 8][pa];
                a[mi][0] = __float_as_uint(fa.x);
                a[mi][1] = __float_as_uint(fb.x);
                a[mi][2] = __float_as_uint(fa.y);
                a[mi][3] = __float_as_uint(fb.y);
            }
#pragma unroll
            for (int ni = 0; ni < 4; ni++) {
                int col = warp_n * 32 + ni * 8 + gID;
                bf[ni][0] = __float_as_uint(ws[kk + t4][col]);
                bf[ni][1] = __float_as_uint(ws[kk + t4 + 4][col]);
            }
#pragma unroll
            for (int mi = 0; mi < 4; mi++)
#pragma unroll
                for (int ni = 0; ni < 4; ni++)
                    mma_tf32(acc[mi][ni][0], acc[mi][ni][1], acc[mi][ni][2], acc[mi][ni][3],
                             a[mi][0], a[mi][1], a[mi][2], a[mi][3],
                             bf[ni][0], bf[ni][1]);
        }
        __syncthreads();
    }

#pragma unroll
    for (int mi = 0; mi < 4; mi++) {
        int r0 = node0 + warp_m * 64 + mi * 16 + gID;
#pragma unroll
        for (int ni = 0; ni < 4; ni++) {
            int cb = warp_n * 32 + ni * 8 + 2 * t4;
            float b0v = bias[cb], b1v = bias[cb + 1];
            if (r0 < NN) {
                out[r0 * HC + cb] = acc[mi][ni][0] + b0v;
                out[r0 * HC + cb + 1] = acc[mi][ni][1] + b1v;
            }
            if (r0 + 8 < NN) {
                out[(r0 + 8) * HC + cb] = acc[mi][ni][2] + b0v;
                out[(r0 + 8) * HC + cb + 1] = acc[mi][ni][3] + b1v;
            }
        }
    }
}

// ---------------- per-node fused edge pass (gather, no atomics) ----------------
// One warp per destination node; 2-way edge unroll (R4 version — 3-way spilled).
template <bool RELU, bool POOL>
__global__ __launch_bounds__(256) void node_edge_kernel(const float* __restrict__ We,
                                                        const int* __restrict__ batch) {
    __shared__ float Wes[EDIM * HC];
    for (int i = threadIdx.x; i < EDIM * HC; i += blockDim.x) Wes[i] = We[i];
    __syncthreads();

    int n = blockIdx.x * 8 + (threadIdx.x >> 5);
    int lane = threadIdx.x & 31;
    if (n >= NN) return;

    int r0 = g_rowptr[n];
    int r1 = g_rowptr[n + 1];

    float qv[NH], acc[NH], asum[NH];
#pragma unroll
    for (int j = 0; j < NH; j++) {
        qv[j] = g_q[n * HC + j * HID + lane];
        acc[j] = 0.f;
        asum[j] = 0.f;
    }

    int i = r0;
    for (; i + 1 < r1; i += 2) {
        int s0 = g_esrc[i], s1 = g_esrc[i + 1];
        float4 a0 = g_eea[i], a1 = g_eea[i + 1];
        float k0[NH], v0[NH], k1[NH], v1[NH];
#pragma unroll
        for (int j = 0; j < NH; j++) {
            int c = j * HID + lane;
            k0[j] = g_k[s0 * HC + c];
            v0[j] = g_v[s0 * HC + c];
            k1[j] = g_k[s1 * HC + c];
            v1[j] = g_v[s1 * HC + c];
        }
        float e0[NH], e1[NH], p0[NH], p1[NH];
#pragma unroll
        for (int j = 0; j < NH; j++) {
            int c = j * HID + lane;
            float w0 = Wes[c], w1 = Wes[HC + c], w2 = Wes[2 * HC + c], w3 = Wes[3 * HC + c];
            e0[j] = a0.x * w0 + a0.y * w1 + a0.z * w2 + a0.w * w3;
            e1[j] = a1.x * w0 + a1.y * w1 + a1.z * w2 + a1.w * w3;
            p0[j] = qv[j] * (k0[j] + e0[j]);
            p1[j] = qv[j] * (k1[j] + e1[j]);
        }
#pragma unroll
        for (int off = 16; off; off >>= 1) {
#pragma unroll
            for (int j = 0; j < NH; j++) {
                p0[j] += __shfl_xor_sync(0xffffffffu, p0[j], off);
                p1[j] += __shfl_xor_sync(0xffffffffu, p1[j], off);
            }
        }
#pragma unroll
        for (int j = 0; j < NH; j++) {
            float al0 = __expf(p0[j] * 0.17677669529663687f);
            float al1 = __expf(p1[j] * 0.17677669529663687f);
            asum[j] += al0 + al1;
            acc[j] = fmaf(v0[j] + e0[j], al0, acc[j]);
            acc[j] = fmaf(v1[j] + e1[j], al1, acc[j]);
        }
    }
    if (i < r1) {
        int s0 = g_esrc[i];
        float4 a0 = g_eea[i];
        float k0[NH], v0[NH], e0[NH], p0[NH];
#pragma unroll
        for (int j = 0; j < NH; j++) {
            int c = j * HID + lane;
            k0[j] = g_k[s0 * HC + c];
            v0[j] = g_v[s0 * HC + c];
        }
#pragma unroll
        for (int j = 0; j < NH; j++) {
            int c = j * HID + lane;
            e0[j] = a0.x * Wes[c] + a0.y * Wes[HC + c] + a0.z * Wes[2 * HC + c] + a0.w * Wes[3 * HC + c];
            p0[j] = qv[j] * (k0[j] + e0[j]);
        }
#pragma unroll
        for (int j = 0; j < NH; j++) {
#pragma unroll
            for (int off = 16; off; off >>= 1) p0[j] += __shfl_xor_sync(0xffffffffu, p0[j], off);
        }
#pragma unroll
        for (int j = 0; j < NH; j++) {
            float al = __expf(p0[j] * 0.17677669529663687f);
            asum[j] += al;
            acc[j] = fmaf(v0[j] + e0[j], al, acc[j]);
        }
    }

    int bslot = POOL ? batch[n] : 0;
#pragma unroll
    for (int j = 0; j < NH; j++) {
        int c = j * HID + lane;
        float h = acc[j] / (asum[j] + 1e-16f) + g_s[n * HC + c];
        if (RELU) h = fmaxf(h, 0.f);
        if (POOL) atomicAdd(&g_pooled[bslot * HC + c], h);
        else g_h[n * HC + c] = h;
    }
}

// ---------------- head ----------------
__global__ void head_kernel(const int* __restrict__ rt,
                            const float* __restrict__ hW,
                            const float* __restrict__ hb,
                            float* __restrict__ out) {
    int b = (blockIdx.x * blockDim.x + threadIdx.x) >> 5;
    int lane = threadIdx.x & 31;
    if (b >= BB) return;
    int r = rt[b];
    float acc = 0.f;
#pragma unroll
    for (int j = 0; j < NH; j++) {
        int c = j * HID + lane;
        acc = fmaf(g_pooled[b * HC + c], hW[r * HC + c], acc);
    }
#pragma unroll
    for (int off = 16; off; off >>= 1) acc += __shfl_xor_sync(0xffffffffu, acc, off);
    if (lane == 0) {
        float cnt = fmaxf(g_cnt[b], 1.f);
        out[b] = acc / cnt + hb[r];
    }
}

// ---------------- launch ----------------
extern "C" void kernel_launch(void* const* d_in, const int* in_sizes, int n_in,
                              void* d_out, int out_size) {
    const float* x     = (const float*)d_in[0];
    const int*   ei    = (const int*)d_in[1];
    const float* ea    = (const float*)d_in[2];
    const int*   batch = (const int*)d_in[3];
    const int*   rt    = (const int*)d_in[4];
    const float* Wq1 = (const float*)d_in[5];
    const float* bq1 = (const float*)d_in[6];
    const float* Wk1 = (const float*)d_in[7];
    const float* bk1 = (const float*)d_in[8];
    const float* Wv1 = (const float*)d_in[9];
    const float* bv1 = (const float*)d_in[10];
    const float* We1 = (const float*)d_in[11];
    const float* Ws1 = (const float*)d_in[12];
    const float* bs1 = (const float*)d_in[13];
    const float* Wq23 = (const float*)d_in[14];
    const float* bq23 = (const float*)d_in[15];
    const float* Wk23 = (const float*)d_in[16];
    const float* bk23 = (const float*)d_in[17];
    const float* Wv23 = (const float*)d_in[18];
    const float* bv23 = (const float*)d_in[19];
    const float* We23 = (const float*)d_in[20];
    const float* Ws23 = (const float*)d_in[21];
    const float* bs23 = (const float*)d_in[22];
    const float* headW = (const float*)d_in[23];
    const float* headb = (const float*)d_in[24];
    float* out = (float*)d_out;

    const dim3 gemm_grid((NN + 127) / 128, 4);
    const int node_blocks = (NN + 7) / 8;

    // ---- fork: first part of CSR build on side stream ----
    cudaEventRecord(g_evA, 0);
    cudaStreamWaitEvent(g_s2, g_evA, 0);
    zero_deg_kernel<<<256, 256, 0, g_s2>>>();       // kernel 1
    hist_kernel<<<1024, 256, 0, g_s2>>>(ei);        // kernel 2
    scanA_kernel<<<SCAN_B, SCAN_T, 0, g_s2>>>();    // kernel 3

    // ---- main stream: layer-1 GEMM enqueued 4th (lands in the profiled slot) ----
    gemm_tc_kernel<64, false><<<gemm_grid, 256>>>(x, Wq1, bq1, Wk1, bk1, Wv1, bv1, Ws1, bs1);  // kernel 4

    // ---- rest of side-stream chain ----
    scanB_kernel<<<1, 256, 0, g_s2>>>();
    scanC_kernel<<<SCAN_B, SCAN_T, 0, g_s2>>>();
    bucket_kernel<<<1024, 256, 0, g_s2>>>(ei, ea);
    zero_pool_kernel<<<256, 256, 0, g_s2>>>();
    cnt_kernel<<<(NN + 255) / 256, 256, 0, g_s2>>>(batch);
    cudaEventRecord(g_evB, g_s2);

    cudaStreamWaitEvent(0, g_evB, 0);  // join before first edge pass
    node_edge_kernel<true, false><<<node_blocks, 256>>>(We1, batch);

    gemm_tc_kernel<128, true><<<gemm_grid, 256>>>(
        x, Wq23, bq23, Wk23, bk23, Wv23, bv23, Ws23, bs23);
    node_edge_kernel<true, false><<<node_blocks, 256>>>(We23, batch);

    gemm_tc_kernel<128, true><<<gemm_grid, 256>>>(
        x, Wq23 + HC * HC, bq23 + HC, Wk23 + HC * HC, bk23 + HC,
        Wv23 + HC * HC, bv23 + HC, Ws23 + HC * HC, bs23 + HC);
    node_edge_kernel<false, true><<<node_blocks, 256>>>(We23 + EDIM * HC, batch);

    head_kernel<<<(BB * 32 + 255) / 256, 256>>>(rt, headW, headb, out);
}

// round 7
// speedup vs baseline: 1.1164x; 1.0635x over previous
#include <cuda_runtime.h>
#include <cstdint>

#define NN 100000
#define EE 500000
#define BB 4096
#define HC 128
#define NH 4
#define HID 32
#define EDIM 4

#define SCAN_T 512
#define SCAN_B ((NN + SCAN_T - 1) / SCAN_T)  // 196

// ---------------- scratch (device globals: allocation-free) ----------------
__device__ float g_q[NN * HC];
__device__ float g_k[NN * HC];
__device__ float g_v[NN * HC];
__device__ float g_s[NN * HC];   // skip (x@Ws + bs)
__device__ float g_h[NN * HC];   // layer output / next-layer input
__device__ float g_pooled[BB * HC];
__device__ float g_cnt[BB];
// CSR build
__device__ int    g_deg[NN];
__device__ int    g_incl[NN];
__device__ int    g_rowptr[NN + 1];
__device__ int    g_cursor[NN];
__device__ int    g_bsum[SCAN_B];
__device__ int    g_boff[SCAN_B];
__device__ int    g_esrc[EE];
__device__ float4 g_eea[EE];

// ---------------- side stream for overlap ----------------
static cudaStream_t g_s2;
static cudaEvent_t g_evA, g_evB;
namespace {
struct StreamInit {
    StreamInit() {
        cudaStreamCreateWithFlags(&g_s2, cudaStreamNonBlocking);
        cudaEventCreateWithFlags(&g_evA, cudaEventDisableTiming);
        cudaEventCreateWithFlags(&g_evB, cudaEventDisableTiming);
    }
} g_stream_init;
}

// ---------------- helpers ----------------
__device__ __forceinline__ float to_tf32(float x) {
    uint32_t u;
    asm("cvt.rna.tf32.f32 %0, %1;" : "=r"(u) : "f"(x));
    return __uint_as_float(u);
}

__device__ __forceinline__ void mma_tf32(float& c0, float& c1, float& c2, float& c3,
                                         uint32_t a0, uint32_t a1, uint32_t a2, uint32_t a3,
                                         uint32_t b0, uint32_t b1) {
    asm volatile(
        "mma.sync.aligned.m16n8k8.row.col.f32.tf32.tf32.f32 "
        "{%0,%1,%2,%3}, {%4,%5,%6,%7}, {%8,%9}, {%0,%1,%2,%3};"
        : "+f"(c0), "+f"(c1), "+f"(c2), "+f"(c3)
        : "r"(a0), "r"(a1), "r"(a2), "r"(a3), "r"(b0), "r"(b1));
}

// ---------------- CSR build ----------------
__global__ void zero_deg_kernel() {
    int stride = gridDim.x * blockDim.x;
    for (int i = blockIdx.x * blockDim.x + threadIdx.x; i < NN; i += stride) g_deg[i] = 0;
}

__global__ void hist_kernel(const int* __restrict__ ei) {
    int stride = gridDim.x * blockDim.x;
    for (int e = blockIdx.x * blockDim.x + threadIdx.x; e < EE; e += stride)
        atomicAdd(&g_deg[ei[EE + e]], 1);
}

__global__ void scanA_kernel() {
    __shared__ int s[SCAN_T];
    int tid = threadIdx.x;
    int i = blockIdx.x * SCAN_T + tid;
    int v = (i < NN) ? g_deg[i] : 0;
    s[tid] = v;
    __syncthreads();
#pragma unroll
    for (int off = 1; off < SCAN_T; off <<= 1) {
        int t = (tid >= off) ? s[tid - off] : 0;
        __syncthreads();
        s[tid] += t;
        __syncthreads();
    }
    if (i < NN) g_incl[i] = s[tid];
    if (tid == SCAN_T - 1) g_bsum[blockIdx.x] = s[tid];
}

__global__ void scanB_kernel() {
    __shared__ int s[256];
    int tid = threadIdx.x;
    int v = (tid < SCAN_B) ? g_bsum[tid] : 0;
    s[tid] = v;
    __syncthreads();
#pragma unroll
    for (int off = 1; off < 256; off <<= 1) {
        int t = (tid >= off) ? s[tid - off] : 0;
        __syncthreads();
        s[tid] += t;
        __syncthreads();
    }
    if (tid < SCAN_B) g_boff[tid] = s[tid] - v;
}

__global__ void scanC_kernel() {
    int i = blockIdx.x * SCAN_T + threadIdx.x;
    if (i < NN) {
        int excl = g_incl[i] - g_deg[i] + g_boff[blockIdx.x];
        g_rowptr[i] = excl;
        g_cursor[i] = excl;
    }
    if (i == 0) g_rowptr[NN] = EE;
}

__global__ void bucket_kernel(const int* __restrict__ ei, const float* __restrict__ ea) {
    int stride = gridDim.x * blockDim.x;
    for (int e = blockIdx.x * blockDim.x + threadIdx.x; e < EE; e += stride) {
        int dst = ei[EE + e];
        int pos = atomicAdd(&g_cursor[dst], 1);
        g_esrc[pos] = ei[e];
        g_eea[pos] = reinterpret_cast<const float4*>(ea)[e];
    }
}

// ---------------- zero pool + count ----------------
__global__ void zero_pool_kernel() {
    int stride = gridDim.x * blockDim.x;
    int i0 = blockIdx.x * blockDim.x + threadIdx.x;
    for (int i = i0; i < BB * HC; i += stride) g_pooled[i] = 0.f;
    for (int i = i0; i < BB; i += stride) g_cnt[i] = 0.f;
}

__global__ void cnt_kernel(const int* __restrict__ batch) {
    int n = blockIdx.x * blockDim.x + threadIdx.x;
    if (n < NN) atomicAdd(&g_cnt[batch[n]], 1.f);
}

// ---------------- tensor-core fused q/k/v/skip GEMM ----------------
// 64x128 block tile (warp tile 32x32), __launch_bounds__(256,2) -> 2 blocks/SM
// (25% occupancy vs 12.5% for the old 128x128 tile at 142 regs).
template <int D, bool USE_H>
__global__ __launch_bounds__(256, 2) void gemm_tc_kernel(
    const float* __restrict__ x,
    const float* __restrict__ Wq, const float* __restrict__ bq,
    const float* __restrict__ Wk, const float* __restrict__ bk,
    const float* __restrict__ Wv, const float* __restrict__ bv,
    const float* __restrict__ Ws, const float* __restrict__ bs) {
    __shared__ __align__(16) float xs[64][36];
    __shared__ __align__(16) float ws[32][136];

    const float* xin = USE_H ? g_h : x;
    const float* W;
    const float* bias;
    float* out;
    int m = blockIdx.y;
    if (m == 0)      { W = Wq; bias = bq; out = g_q; }
    else if (m == 1) { W = Wk; bias = bk; out = g_k; }
    else if (m == 2) { W = Wv; bias = bv; out = g_v; }
    else             { W = Ws; bias = bs; out = g_s; }

    int node0 = blockIdx.x * 64;
    int tid = threadIdx.x;
    int lane = tid & 31, wid = tid >> 5;
    int warp_m = wid >> 2, warp_n = wid & 3;  // 2 x 4, warp tile 32x32
    int gID = lane >> 2, t4 = lane & 3;

    // per-thread load coordinates
    const int xr_r[2] = {(tid + 0) >> 3, (tid + 256) >> 3};
    const int xr_c = (tid & 7) * 4;
    const int wr_r[4] = {(tid + 0) >> 5, (tid + 256) >> 5, (tid + 512) >> 5, (tid + 768) >> 5};
    const int wr_c = (tid & 31) * 4;

    float4 xr[2], wr[4];
    auto load_chunk = [&](int k0) {
#pragma unroll
        for (int t = 0; t < 2; t++) {
            int n = node0 + xr_r[t];
            xr[t] = (n < NN) ? *(const float4*)&xin[n * D + k0 + xr_c]
                             : make_float4(0.f, 0.f, 0.f, 0.f);
        }
#pragma unroll
        for (int t = 0; t < 4; t++)
            wr[t] = *(const float4*)&W[(k0 + wr_r[t]) * HC + wr_c];
    };
    auto store_chunk = [&]() {
#pragma unroll
        for (int t = 0; t < 2; t++) {
            float* xp = &xs[xr_r[t]][xr_c];
            xp[0] = to_tf32(xr[t].x); xp[1] = to_tf32(xr[t].y);
            xp[2] = to_tf32(xr[t].z); xp[3] = to_tf32(xr[t].w);
        }
#pragma unroll
        for (int t = 0; t < 4; t++) {
            float* wp = &ws[wr_r[t]][wr_c];
            wp[0] = to_tf32(wr[t].x); wp[1] = to_tf32(wr[t].y);
            wp[2] = to_tf32(wr[t].z); wp[3] = to_tf32(wr[t].w);
        }
    };

    float acc[2][4][4];
#pragma unroll
    for (int mi = 0; mi < 2; mi++)
#pragma unroll
        for (int ni = 0; ni < 4; ni++)
#pragma unroll
            for (int r = 0; r < 4; r++) acc[mi][ni][r] = 0.f;

    load_chunk(0);
#pragma unroll
    for (int k0 = 0; k0 < D; k0 += 32) {
        store_chunk();
        __syncthreads();
        if (k0 + 32 < D) load_chunk(k0 + 32);  // prefetch overlaps mma below

#pragma unroll
        for (int ks = 0; ks < 4; ks++) {
            int kk = ks * 8;
            uint32_t a[2][4], bf[4][2];
#pragma unroll
            for (int mi = 0; mi < 2; mi++) {
                int row = warp_m * 32 + mi * 16 + gID;
                a[mi][0] = __float_as_uint(xs[row][kk + t4]);
                a[mi][1] = __float_as_uint(xs[row + 8][kk + t4]);
                a[mi][2] = __float_as_uint(xs[row][kk + t4 + 4]);
                a[mi][3] = __float_as_uint(xs[row + 8][kk + t4 + 4]);
            }
#pragma unroll
            for (int ni = 0; ni < 4; ni++) {
                int col = warp_n * 32 + ni * 8 + gID;
                bf[ni][0] = __float_as_uint(ws[kk + t4][col]);
                bf[ni][1] = __float_as_uint(ws[kk + t4 + 4][col]);
            }
#pragma unroll
            for (int mi = 0; mi < 2; mi++)
#pragma unroll
                for (int ni = 0; ni < 4; ni++)
                    mma_tf32(acc[mi][ni][0], acc[mi][ni][1], acc[mi][ni][2], acc[mi][ni][3],
                             a[mi][0], a[mi][1], a[mi][2], a[mi][3],
                             bf[ni][0], bf[ni][1]);
        }
        __syncthreads();
    }

#pragma unroll
    for (int mi = 0; mi < 2; mi++) {
        int r0 = node0 + warp_m * 32 + mi * 16 + gID;
#pragma unroll
        for (int ni = 0; ni < 4; ni++) {
            int cb = warp_n * 32 + ni * 8 + 2 * t4;
            float b0v = bias[cb], b1v = bias[cb + 1];
            if (r0 < NN) {
                out[r0 * HC + cb] = acc[mi][ni][0] + b0v;
                out[r0 * HC + cb + 1] = acc[mi][ni][1] + b1v;
            }
            if (r0 + 8 < NN) {
                out[(r0 + 8) * HC + cb] = acc[mi][ni][2] + b0v;
                out[(r0 + 8) * HC + cb + 1] = acc[mi][ni][3] + b1v;
            }
        }
    }
}

// ---------------- per-node fused edge pass (gather, no atomics) ----------------
// One warp per destination node; 2-way edge unroll.
template <bool RELU, bool POOL>
__global__ __launch_bounds__(256) void node_edge_kernel(const float* __restrict__ We,
                                                        const int* __restrict__ batch) {
    __shared__ float Wes[EDIM * HC];
    for (int i = threadIdx.x; i < EDIM * HC; i += blockDim.x) Wes[i] = We[i];
    __syncthreads();

    int n = blockIdx.x * 8 + (threadIdx.x >> 5);
    int lane = threadIdx.x & 31;
    if (n >= NN) return;

    int r0 = g_rowptr[n];
    int r1 = g_rowptr[n + 1];

    float qv[NH], acc[NH], asum[NH];
#pragma unroll
    for (int j = 0; j < NH; j++) {
        qv[j] = g_q[n * HC + j * HID + lane];
        acc[j] = 0.f;
        asum[j] = 0.f;
    }

    int i = r0;
    for (; i + 1 < r1; i += 2) {
        int s0 = g_esrc[i], s1 = g_esrc[i + 1];
        float4 a0 = g_eea[i], a1 = g_eea[i + 1];
        float k0[NH], v0[NH], k1[NH], v1[NH];
#pragma unroll
        for (int j = 0; j < NH; j++) {
            int c = j * HID + lane;
            k0[j] = g_k[s0 * HC + c];
            v0[j] = g_v[s0 * HC + c];
            k1[j] = g_k[s1 * HC + c];
            v1[j] = g_v[s1 * HC + c];
        }
        float e0[NH], e1[NH], p0[NH], p1[NH];
#pragma unroll
        for (int j = 0; j < NH; j++) {
            int c = j * HID + lane;
            float w0 = Wes[c], w1 = Wes[HC + c], w2 = Wes[2 * HC + c], w3 = Wes[3 * HC + c];
            e0[j] = a0.x * w0 + a0.y * w1 + a0.z * w2 + a0.w * w3;
            e1[j] = a1.x * w0 + a1.y * w1 + a1.z * w2 + a1.w * w3;
            p0[j] = qv[j] * (k0[j] + e0[j]);
            p1[j] = qv[j] * (k1[j] + e1[j]);
        }
#pragma unroll
        for (int off = 16; off; off >>= 1) {
#pragma unroll
            for (int j = 0; j < NH; j++) {
                p0[j] += __shfl_xor_sync(0xffffffffu, p0[j], off);
                p1[j] += __shfl_xor_sync(0xffffffffu, p1[j], off);
            }
        }
#pragma unroll
        for (int j = 0; j < NH; j++) {
            float al0 = __expf(p0[j] * 0.17677669529663687f);
            float al1 = __expf(p1[j] * 0.17677669529663687f);
            asum[j] += al0 + al1;
            acc[j] = fmaf(v0[j] + e0[j], al0, acc[j]);
            acc[j] = fmaf(v1[j] + e1[j], al1, acc[j]);
        }
    }
    if (i < r1) {
        int s0 = g_esrc[i];
        float4 a0 = g_eea[i];
        float k0[NH], v0[NH], e0[NH], p0[NH];
#pragma unroll
        for (int j = 0; j < NH; j++) {
            int c = j * HID + lane;
            k0[j] = g_k[s0 * HC + c];
            v0[j] = g_v[s0 * HC + c];
        }
#pragma unroll
        for (int j = 0; j < NH; j++) {
            int c = j * HID + lane;
            e0[j] = a0.x * Wes[c] + a0.y * Wes[HC + c] + a0.z * Wes[2 * HC + c] + a0.w * Wes[3 * HC + c];
            p0[j] = qv[j] * (k0[j] + e0[j]);
        }
#pragma unroll
        for (int j = 0; j < NH; j++) {
#pragma unroll
            for (int off = 16; off; off >>= 1) p0[j] += __shfl_xor_sync(0xffffffffu, p0[j], off);
        }
#pragma unroll
        for (int j = 0; j < NH; j++) {
            float al = __expf(p0[j] * 0.17677669529663687f);
            asum[j] += al;
            acc[j] = fmaf(v0[j] + e0[j], al, acc[j]);
        }
    }

    int bslot = POOL ? batch[n] : 0;
#pragma unroll
    for (int j = 0; j < NH; j++) {
        int c = j * HID + lane;
        float h = acc[j] / (asum[j] + 1e-16f) + g_s[n * HC + c];
        if (RELU) h = fmaxf(h, 0.f);
        if (POOL) atomicAdd(&g_pooled[bslot * HC + c], h);
        else g_h[n * HC + c] = h;
    }
}

// ---------------- head ----------------
__global__ void head_kernel(const int* __restrict__ rt,
                            const float* __restrict__ hW,
                            const float* __restrict__ hb,
                            float* __restrict__ out) {
    int b = (blockIdx.x * blockDim.x + threadIdx.x) >> 5;
    int lane = threadIdx.x & 31;
    if (b >= BB) return;
    int r = rt[b];
    float acc = 0.f;
#pragma unroll
    for (int j = 0; j < NH; j++) {
        int c = j * HID + lane;
        acc = fmaf(g_pooled[b * HC + c], hW[r * HC + c], acc);
    }
#pragma unroll
    for (int off = 16; off; off >>= 1) acc += __shfl_xor_sync(0xffffffffu, acc, off);
    if (lane == 0) {
        float cnt = fmaxf(g_cnt[b], 1.f);
        out[b] = acc / cnt + hb[r];
    }
}

// ---------------- launch ----------------
extern "C" void kernel_launch(void* const* d_in, const int* in_sizes, int n_in,
                              void* d_out, int out_size) {
    const float* x     = (const float*)d_in[0];
    const int*   ei    = (const int*)d_in[1];
    const float* ea    = (const float*)d_in[2];
    const int*   batch = (const int*)d_in[3];
    const int*   rt    = (const int*)d_in[4];
    const float* Wq1 = (const float*)d_in[5];
    const float* bq1 = (const float*)d_in[6];
    const float* Wk1 = (const float*)d_in[7];
    const float* bk1 = (const float*)d_in[8];
    const float* Wv1 = (const float*)d_in[9];
    const float* bv1 = (const float*)d_in[10];
    const float* We1 = (const float*)d_in[11];
    const float* Ws1 = (const float*)d_in[12];
    const float* bs1 = (const float*)d_in[13];
    const float* Wq23 = (const float*)d_in[14];
    const float* bq23 = (const float*)d_in[15];
    const float* Wk23 = (const float*)d_in[16];
    const float* bk23 = (const float*)d_in[17];
    const float* Wv23 = (const float*)d_in[18];
    const float* bv23 = (const float*)d_in[19];
    const float* We23 = (const float*)d_in[20];
    const float* Ws23 = (const float*)d_in[21];
    const float* bs23 = (const float*)d_in[22];
    const float* headW = (const float*)d_in[23];
    const float* headb = (const float*)d_in[24];
    float* out = (float*)d_out;

    const dim3 gemm_grid((NN + 63) / 64, 4);
    const int node_blocks = (NN + 7) / 8;

    // ---- fork: first part of CSR build on side stream ----
    cudaEventRecord(g_evA, 0);
    cudaStreamWaitEvent(g_s2, g_evA, 0);
    zero_deg_kernel<<<256, 256, 0, g_s2>>>();       // kernel 1
    hist_kernel<<<1024, 256, 0, g_s2>>>(ei);        // kernel 2
    scanA_kernel<<<SCAN_B, SCAN_T, 0, g_s2>>>();    // kernel 3

    // ---- main stream: layer-1 GEMM enqueued 4th (profiled slot) ----
    gemm_tc_kernel<64, false><<<gemm_grid, 256>>>(x, Wq1, bq1, Wk1, bk1, Wv1, bv1, Ws1, bs1);

    // ---- rest of side-stream chain ----
    scanB_kernel<<<1, 256, 0, g_s2>>>();
    scanC_kernel<<<SCAN_B, SCAN_T, 0, g_s2>>>();
    bucket_kernel<<<1024, 256, 0, g_s2>>>(ei, ea);
    zero_pool_kernel<<<256, 256, 0, g_s2>>>();
    cnt_kernel<<<(NN + 255) / 256, 256, 0, g_s2>>>(batch);
    cudaEventRecord(g_evB, g_s2);

    cudaStreamWaitEvent(0, g_evB, 0);  // join before first edge pass
    node_edge_kernel<true, false><<<node_blocks, 256>>>(We1, batch);

    gemm_tc_kernel<128, true><<<gemm_grid, 256>>>(
        x, Wq23, bq23, Wk23, bk23, Wv23, bv23, Ws23, bs23);
    node_edge_kernel<true, false><<<node_blocks, 256>>>(We23, batch);

    gemm_tc_kernel<128, true><<<gemm_grid, 256>>>(
        x, Wq23 + HC * HC, bq23 + HC, Wk23 + HC * HC, bk23 + HC,
        Wv23 + HC * HC, bv23 + HC, Ws23 + HC * HC, bs23 + HC);
    node_edge_kernel<false, true><<<node_blocks, 256>>>(We23 + EDIM * HC, batch);

    head_kernel<<<(BB * 32 + 255) / 256, 256>>>(rt, headW, headb, out);
}